// round 11
// baseline (speedup 1.0000x reference)
#include <cuda_runtime.h>
#include <cuda_fp16.h>
#include <cstdint>
#include <cstddef>

// ===================== problem constants =====================
#define BB   4096
#define HH   2048
#define VV   32000
#define HALF (BB/2)

#define BM   128
#define BN   256
#define BK   64          // fp16 elems per K tile = 128 bytes per row
#define NKT  (HH/BK)     // 32
#define NVCH (VV/BN)     // 125
#define NMT  (BB/BM)     // 32
#define NTHREADS 512     // 16 warps: 4 (M) x 4 (N), warp tile 32x64

#define STAGES   3
#define STAGE_BYTES  (16384 + 32768)            // A 128x128B + B 256x128B
#define SM_RED   (STAGES * STAGE_BYTES)         // 147456
#define SM_BYTES (SM_RED + 2 * 2048)            // + redS[4][128], redE[4][128]
#define SM_ALLOC (SM_BYTES + 1024)

// ===================== device scratch (static — no runtime allocs) =====================
__device__ alignas(256) __half g_xb[(size_t)BB * HH];          // 16 MB
__device__ alignas(256) __half g_wb[(size_t)VV * HH];          // 131 MB
__device__ alignas(256) float g_psum[(size_t)NVCH * BB];       // 2 MB
__device__ alignas(256) float g_psexp[(size_t)NVCH * BB];      // 2 MB
__device__ alignas(256) float g_t[BB];
__device__ alignas(256) float g_allp[BB];
__device__ alignas(256) float g_nll[HALF];
__device__ alignas(256) float g_vld[HALF];

// ===================== helpers =====================
__device__ __forceinline__ uint32_t smem_u32(const void* p) {
    uint32_t a;
    asm("{ .reg .u64 t; cvta.to.shared.u64 t, %1; cvt.u32.u64 %0, t; }" : "=r"(a) : "l"(p));
    return a;
}

__device__ __forceinline__ void cp_async16(uint32_t smem_dst, const void* gmem_src) {
    asm volatile("cp.async.cg.shared.global [%0], [%1], 16;"
                 :: "r"(smem_dst), "l"(gmem_src) : "memory");
}
#define CP_COMMIT() asm volatile("cp.async.commit_group;" ::: "memory")
#define CP_WAIT(N)  asm volatile("cp.async.wait_group %0;" :: "n"(N) : "memory")

__device__ __forceinline__ void ldmatrix_x4(uint32_t* r, uint32_t addr) {
    asm volatile("ldmatrix.sync.aligned.m8n8.x4.shared.b16 {%0,%1,%2,%3}, [%4];"
                 : "=r"(r[0]), "=r"(r[1]), "=r"(r[2]), "=r"(r[3]) : "r"(addr));
}

__device__ __forceinline__ void mma16816(float* c, const uint32_t* a, const uint32_t* b) {
    asm volatile(
        "mma.sync.aligned.m16n8k16.row.col.f32.f16.f16.f32 "
        "{%0,%1,%2,%3}, {%4,%5,%6,%7}, {%8,%9}, {%0,%1,%2,%3};"
        : "+f"(c[0]), "+f"(c[1]), "+f"(c[2]), "+f"(c[3])
        : "r"(a[0]), "r"(a[1]), "r"(a[2]), "r"(a[3]), "r"(b[0]), "r"(b[1]));
}

// ===================== fp32 -> fp16 conversion =====================
__global__ void cvt_x_kernel(const float* __restrict__ x) {
    size_t n4 = (size_t)BB * HH / 4;
    for (size_t i = (size_t)blockIdx.x * blockDim.x + threadIdx.x; i < n4;
         i += (size_t)gridDim.x * blockDim.x) {
        float4 f = ((const float4*)x)[i];
        __half2* d = (__half2*)g_xb;
        d[2*i]     = __floats2half2_rn(f.x, f.y);
        d[2*i + 1] = __floats2half2_rn(f.z, f.w);
    }
}

__global__ void cvt_w_kernel(const float* __restrict__ W) {
    size_t n4 = (size_t)VV * HH / 4;
    for (size_t i = (size_t)blockIdx.x * blockDim.x + threadIdx.x; i < n4;
         i += (size_t)gridDim.x * blockDim.x) {
        float4 f = ((const float4*)W)[i];
        __half2* d = (__half2*)g_wb;
        d[2*i]     = __floats2half2_rn(f.x, f.y);
        d[2*i + 1] = __floats2half2_rn(f.z, f.w);
    }
}

// ===================== exact fp32 target logit: t_b = x_b . W[y_b] =====================
// Warp per row, plain scalar coalesced loads. Sole writer of g_t.
__global__ void target_kernel(const float* __restrict__ x, const float* __restrict__ W,
                              const long long* __restrict__ y) {
    int w   = (blockIdx.x * blockDim.x + threadIdx.x) >> 5;  // row
    int lid = threadIdx.x & 31;
    if (w >= HALF) return;
    long long yv = y[w];
    if (yv < 0 || yv >= VV) { if (lid == 0) g_t[w] = 0.f; return; }
    const float* xr = x + (size_t)w * HH;
    const float* wr = W + (size_t)yv * HH;
    float s = 0.f;
    for (int h = lid; h < HH; h += 32) s += xr[h] * wr[h];
    #pragma unroll
    for (int o = 16; o > 0; o >>= 1) s += __shfl_xor_sync(0xFFFFFFFFu, s, o);
    if (lid == 0) g_t[w] = s;
}

// ===================== main GEMM + fused rowwise (sum, sumexp) epilogue =====================
// grid = NVCH*NMT; bid = v*NMT + m so concurrent CTAs share W tiles in L2.
// 16 warps, warp (wm, wn) owns a 32x64 sub-tile of the 128x256 C tile.
__global__ void __launch_bounds__(NTHREADS, 1)
gemm_lse_kernel() {
    extern __shared__ char smem_dyn[];
    char* smc = (char*)(((uintptr_t)smem_dyn + 1023) & ~(uintptr_t)1023);
    uint32_t sb = smem_u32(smc);

    const int tid = threadIdx.x;
    const int wid = tid >> 5, lid = tid & 31;
    const int wm = wid & 3, wn = wid >> 2;
    const int m = blockIdx.x % NMT;
    const int v = blockIdx.x / NMT;

    const char* Ag = (const char*)g_xb + (size_t)m * BM * (HH * 2);
    const char* Bg = (const char*)g_wb + (size_t)v * BN * (HH * 2);

    float acc[2][8][4];
    #pragma unroll
    for (int i = 0; i < 2; i++)
        #pragma unroll
        for (int j = 0; j < 8; j++)
            #pragma unroll
            for (int c = 0; c < 4; c++) acc[i][j][c] = 0.0f;

    // ---- tile loader (A: 1024 x 16B chunks, B: 2048 x 16B chunks) ----
    auto load_tile = [&](int kt, int st) {
        uint32_t sA = sb + st * STAGE_BYTES;
        uint32_t sB = sA + 16384;
        const char* a_src = Ag + kt * 128;   // kt*BK*2 bytes into the K dim
        const char* b_src = Bg + kt * 128;
        #pragma unroll
        for (int c = tid; c < 1024; c += NTHREADS) {
            int r = c >> 3, seg = c & 7;
            uint32_t dst = sA + (uint32_t)(r * 128 + ((seg * 16) ^ ((r & 7) << 4)));
            cp_async16(dst, a_src + (size_t)r * 4096 + seg * 16);
        }
        #pragma unroll
        for (int c = tid; c < 2048; c += NTHREADS) {
            int r = c >> 3, seg = c & 7;
            uint32_t dst = sB + (uint32_t)(r * 128 + ((seg * 16) ^ ((r & 7) << 4)));
            cp_async16(dst, b_src + (size_t)r * 4096 + seg * 16);
        }
        CP_COMMIT();
    };

    // ---- prologue: stages 0,1 ----
    load_tile(0, 0);
    load_tile(1, 1);

    // ---- mainloop ----
    for (int kt = 0; kt < NKT; kt++) {
        int st = kt % STAGES;
        // On the last tile no newer group follows it: must drain fully.
        if (kt + 1 < NKT) { CP_WAIT(1); } else { CP_WAIT(0); }
        __syncthreads();            // all warps done with stage (kt-1) -> safe to overwrite
        if (kt + 2 < NKT) load_tile(kt + 2, (kt + 2) % STAGES);

        uint32_t sA = sb + st * STAGE_BYTES;
        uint32_t sB = sA + 16384;

        #pragma unroll
        for (int ks = 0; ks < 4; ks++) {        // 4 x k16 per 64-wide K tile
            uint32_t af[2][4], bf[4][4];
            #pragma unroll
            for (int i = 0; i < 2; i++) {
                int row = wm * 32 + i * 16 + (lid & 15);
                int kb  = ks * 32 + ((lid >> 4) << 4);
                ldmatrix_x4(af[i], sA + (uint32_t)(row * 128 + (kb ^ ((row & 7) << 4))));
            }
            #pragma unroll
            for (int p = 0; p < 4; p++) {       // frag pair (2p, 2p+1)
                int n  = wn * 64 + p * 16 + (lid & 7) + (((lid >> 4) & 1) << 3);
                int kb = ks * 32 + (((lid >> 3) & 1) << 4);
                ldmatrix_x4(bf[p], sB + (uint32_t)(n * 128 + (kb ^ ((n & 7) << 4))));
            }
            #pragma unroll
            for (int i = 0; i < 2; i++)
                #pragma unroll
                for (int p = 0; p < 4; p++) {
                    mma16816(acc[i][2 * p],     af[i], &bf[p][0]);
                    mma16816(acc[i][2 * p + 1], af[i], &bf[p][2]);
                }
        }
    }

    // ---- epilogue: per-row sum / sumexp ----
    float* redS = (float*)(smc + SM_RED);            // [4][128]
    float* redE = redS + 4 * 128;                    // [4][128]
    __syncthreads();                                 // done with stage buffers
    for (int i = tid; i < 4 * 128; i += NTHREADS) { redS[i] = 0.f; redE[i] = 0.f; }
    __syncthreads();

    const int g = lid >> 2, q = lid & 3;
    #pragma unroll
    for (int i = 0; i < 2; i++) {
        #pragma unroll
        for (int half = 0; half < 2; half++) {
            int r = wm * 32 + i * 16 + g + half * 8;      // local row in [0,128)
            float s = 0.f, se = 0.f;
            #pragma unroll
            for (int j = 0; j < 8; j++) {
                float v0 = acc[i][j][half * 2 + 0];
                float v1 = acc[i][j][half * 2 + 1];
                s  += v0 + v1;
                se += __expf(v0) + __expf(v1);
            }
            s  += __shfl_xor_sync(0xFFFFFFFFu, s, 1);
            s  += __shfl_xor_sync(0xFFFFFFFFu, s, 2);
            se += __shfl_xor_sync(0xFFFFFFFFu, se, 1);
            se += __shfl_xor_sync(0xFFFFFFFFu, se, 2);
            if (q == 0) {
                redS[wn * 128 + r] = s;      // unique writer per slot
                redE[wn * 128 + r] = se;
            }
        }
    }
    __syncthreads();

    if (tid < 128) {
        int r = tid;
        float s  = redS[r] + redS[128 + r] + redS[256 + r] + redS[384 + r];
        float se = redE[r] + redE[128 + r] + redE[256 + r] + redE[384 + r];
        g_psum [(size_t)v * BB + m * BM + r] = s;
        g_psexp[(size_t)v * BB + m * BM + r] = se;
    }
}

// ===================== reductions =====================
__global__ void reduce_rows_kernel(const long long* __restrict__ y) {
    int row = blockIdx.x * blockDim.x + threadIdx.x;
    if (row >= BB) return;
    float se = 0.f, s = 0.f;
    for (int c = 0; c < NVCH; c++) {
        se += g_psexp[(size_t)c * BB + row];
        s  += g_psum [(size_t)c * BB + row];
    }
    float lse = logf(se);
    g_allp[row] = s * (1.0f / (float)VV) - lse;
    if (row < HALF) {
        bool valid = (y[row] != -100);
        g_nll[row] = valid ? (lse - g_t[row]) : 0.0f;
        g_vld[row] = valid ? 1.0f : 0.0f;
    }
}

__global__ void finalize_kernel(float* out) {
    __shared__ float sh1[256], sh2[256], sh3[256];
    int tid = threadIdx.x;
    float ce = 0.f, orx = 0.f, vc = 0.f;
    for (int i = tid; i < HALF; i += 256) {
        ce += g_nll[i];
        vc += g_vld[i];
        float ch = g_allp[i];
        float rj = g_allp[i + HALF];
        float lo = (ch - rj) - (log1pf(-expf(ch)) - log1pf(-expf(rj)));
        float ls = fminf(lo, 0.f) - log1pf(expf(-fabsf(lo)));   // log_sigmoid
        orx += 0.1f * ls;
    }
    sh1[tid] = ce; sh2[tid] = orx; sh3[tid] = vc;
    __syncthreads();
    for (int s = 128; s > 0; s >>= 1) {
        if (tid < s) { sh1[tid] += sh1[tid+s]; sh2[tid] += sh2[tid+s]; sh3[tid] += sh3[tid+s]; }
        __syncthreads();
    }
    if (tid == 0) {
        float denom = fmaxf(sh3[0], 1.0f);
        out[0] = sh1[0] / denom - sh2[0] / (float)HALF;
    }
}

// ===================== launch =====================
extern "C" void kernel_launch(void* const* d_in, const int* in_sizes, int n_in,
                              void* d_out, int out_size) {
    const float*     x = (const float*)d_in[0];
    const float*     W = (const float*)d_in[1];
    const long long* y = (const long long*)d_in[2];
    float* out = (float*)d_out;
    (void)in_sizes; (void)n_in; (void)out_size;

    cvt_x_kernel<<<2048, 256>>>(x);
    cvt_w_kernel<<<8192, 256>>>(W);

    cudaFuncSetAttribute(gemm_lse_kernel,
                         cudaFuncAttributeMaxDynamicSharedMemorySize, SM_ALLOC);
    gemm_lse_kernel<<<NVCH * NMT, NTHREADS, SM_ALLOC>>>();

    // Exact fp32 target logits (sole writer of g_t).
    target_kernel<<<(HALF * 32) / 256, 256>>>(x, W, y);

    reduce_rows_kernel<<<BB / 256, 256>>>(y);
    finalize_kernel<<<1, 256>>>(out);
}

// round 14
// speedup vs baseline: 1.1104x; 1.1104x over previous
#include <cuda_runtime.h>
#include <cuda_fp16.h>
#include <cstdint>
#include <cstddef>

// ===================== problem constants =====================
#define BB   4096
#define HH   2048
#define VV   32000
#define HALF (BB/2)

#define BM   128
#define BN   256
#define NVCH (VV/BN)     // 125
#define NMT  (BB/BM)     // 32
#define NTHREADS 512     // 16 warps: 4 (M) x 4 (N), warp tile 32x64

// K pipeline: stage = 2 sub-tiles of K=64 (identical layout to the proven BK=64
// tile: A 128x128B + B 256x128B = 48KB each). 16 outer iterations, half the syncs.
#define NST      16                              // outer stages (K=128 each)
#define SUB_BYTES    49152                       // 16384 (A) + 32768 (B)
#define STAGE_BYTES  (2 * SUB_BYTES)             // 98304
#define STAGES   2
#define SM_RED   (STAGES * STAGE_BYTES)          // 196608
#define SM_BYTES (SM_RED + 2 * 2048)             // + redS[4][128], redE[4][128]
#define SM_ALLOC (SM_BYTES + 1024)

// ===================== device scratch (static — no runtime allocs) =====================
__device__ alignas(256) __half g_xb[(size_t)BB * HH];          // 16 MB
__device__ alignas(256) __half g_wb[(size_t)VV * HH];          // 131 MB
__device__ alignas(256) float g_psum[(size_t)NVCH * BB];       // 2 MB
__device__ alignas(256) float g_psexp[(size_t)NVCH * BB];      // 2 MB
__device__ alignas(256) float g_t[BB];
__device__ alignas(256) float g_allp[BB];
__device__ alignas(256) float g_nll[HALF];
__device__ alignas(256) float g_vld[HALF];

// ===================== helpers =====================
__device__ __forceinline__ uint32_t smem_u32(const void* p) {
    uint32_t a;
    asm("{ .reg .u64 t; cvta.to.shared.u64 t, %1; cvt.u32.u64 %0, t; }" : "=r"(a) : "l"(p));
    return a;
}

__device__ __forceinline__ void cp_async16(uint32_t smem_dst, const void* gmem_src) {
    asm volatile("cp.async.cg.shared.global [%0], [%1], 16;"
                 :: "r"(smem_dst), "l"(gmem_src) : "memory");
}
#define CP_COMMIT() asm volatile("cp.async.commit_group;" ::: "memory")
#define CP_WAIT(N)  asm volatile("cp.async.wait_group %0;" :: "n"(N) : "memory")

__device__ __forceinline__ void ldmatrix_x4(uint32_t* r, uint32_t addr) {
    asm volatile("ldmatrix.sync.aligned.m8n8.x4.shared.b16 {%0,%1,%2,%3}, [%4];"
                 : "=r"(r[0]), "=r"(r[1]), "=r"(r[2]), "=r"(r[3]) : "r"(addr));
}

__device__ __forceinline__ void mma16816(float* c, const uint32_t* a, const uint32_t* b) {
    asm volatile(
        "mma.sync.aligned.m16n8k16.row.col.f32.f16.f16.f32 "
        "{%0,%1,%2,%3}, {%4,%5,%6,%7}, {%8,%9}, {%0,%1,%2,%3};"
        : "+f"(c[0]), "+f"(c[1]), "+f"(c[2]), "+f"(c[3])
        : "r"(a[0]), "r"(a[1]), "r"(a[2]), "r"(a[3]), "r"(b[0]), "r"(b[1]));
}

// ===================== fp32 -> fp16 conversion =====================
__global__ void cvt_x_kernel(const float* __restrict__ x) {
    size_t n4 = (size_t)BB * HH / 4;
    for (size_t i = (size_t)blockIdx.x * blockDim.x + threadIdx.x; i < n4;
         i += (size_t)gridDim.x * blockDim.x) {
        float4 f = ((const float4*)x)[i];
        __half2* d = (__half2*)g_xb;
        d[2*i]     = __floats2half2_rn(f.x, f.y);
        d[2*i + 1] = __floats2half2_rn(f.z, f.w);
    }
}

__global__ void cvt_w_kernel(const float* __restrict__ W) {
    size_t n4 = (size_t)VV * HH / 4;
    for (size_t i = (size_t)blockIdx.x * blockDim.x + threadIdx.x; i < n4;
         i += (size_t)gridDim.x * blockDim.x) {
        float4 f = ((const float4*)W)[i];
        __half2* d = (__half2*)g_wb;
        d[2*i]     = __floats2half2_rn(f.x, f.y);
        d[2*i + 1] = __floats2half2_rn(f.z, f.w);
    }
}

// ===================== exact fp32 target logit: t_b = x_b . W[y_b] =====================
// Warp per row. Sole writer of g_t. Independent of the GEMM (runs before it so the
// GEMM lands at launch index 3, which is where ncu's capture window falls).
__global__ void target_kernel(const float* __restrict__ x, const float* __restrict__ W,
                              const long long* __restrict__ y) {
    int w   = (blockIdx.x * blockDim.x + threadIdx.x) >> 5;  // row
    int lid = threadIdx.x & 31;
    if (w >= HALF) return;
    long long yv = y[w];
    if (yv < 0 || yv >= VV) { if (lid == 0) g_t[w] = 0.f; return; }
    const float* xr = x + (size_t)w * HH;
    const float* wr = W + (size_t)yv * HH;
    float s = 0.f;
    for (int h = lid; h < HH; h += 32) s += xr[h] * wr[h];
    #pragma unroll
    for (int o = 16; o > 0; o >>= 1) s += __shfl_xor_sync(0xFFFFFFFFu, s, o);
    if (lid == 0) g_t[w] = s;
}

// ===================== main GEMM + fused rowwise (sum, sumexp) epilogue =====================
// grid = NVCH*NMT; bid = v*NMT + m so concurrent CTAs share W tiles in L2.
// 16 warps, warp (wm, wn) owns a 32x64 sub-tile of the 128x256 C tile.
// Accumulation order is IDENTICAL to the passing round-11 kernel (k ascending,
// same mma sequence per accumulator) -> rel_err reproduces exactly.
__global__ void __launch_bounds__(NTHREADS, 1)
gemm_lse_kernel() {
    extern __shared__ char smem_dyn[];
    char* smc = (char*)(((uintptr_t)smem_dyn + 1023) & ~(uintptr_t)1023);
    uint32_t sb = smem_u32(smc);

    const int tid = threadIdx.x;
    const int wid = tid >> 5, lid = tid & 31;
    const int wm = wid & 3, wn = wid >> 2;
    const int m = blockIdx.x % NMT;
    const int v = blockIdx.x / NMT;

    const char* Ag = (const char*)g_xb + (size_t)m * BM * (HH * 2);
    const char* Bg = (const char*)g_wb + (size_t)v * BN * (HH * 2);

    float acc[2][8][4];
    #pragma unroll
    for (int i = 0; i < 2; i++)
        #pragma unroll
        for (int j = 0; j < 8; j++)
            #pragma unroll
            for (int c = 0; c < 4; c++) acc[i][j][c] = 0.0f;

    // ---- sub-tile loader: j = global K=64 sub-tile index (0..31) ----
    auto load_sub = [&](int j, uint32_t dst) {
        const char* a_src = Ag + j * 128;     // j*64 fp16 into the K dim
        const char* b_src = Bg + j * 128;
        #pragma unroll
        for (int c = tid; c < 1024; c += NTHREADS) {
            int r = c >> 3, seg = c & 7;
            uint32_t d = dst + (uint32_t)(r * 128 + ((seg * 16) ^ ((r & 7) << 4)));
            cp_async16(d, a_src + (size_t)r * 4096 + seg * 16);
        }
        #pragma unroll
        for (int c = tid; c < 2048; c += NTHREADS) {
            int r = c >> 3, seg = c & 7;
            uint32_t d = dst + 16384 + (uint32_t)(r * 128 + ((seg * 16) ^ ((r & 7) << 4)));
            cp_async16(d, b_src + (size_t)r * 4096 + seg * 16);
        }
    };
    auto load_stage = [&](int kt, int st) {     // K=128 stage = sub-tiles 2kt, 2kt+1
        uint32_t base = sb + st * STAGE_BYTES;
        load_sub(2 * kt,     base);
        load_sub(2 * kt + 1, base + SUB_BYTES);
        CP_COMMIT();
    };

    // ---- prologue ----
    load_stage(0, 0);

    // ---- mainloop: 16 outer stages (half the syncs of the 32-tile version) ----
    for (int kt = 0; kt < NST; kt++) {
        CP_WAIT(0);                 // stage kt fully arrived (this thread's chunks)
        __syncthreads();            // all threads' chunks visible; prev compute done
        if (kt + 1 < NST) load_stage(kt + 1, (kt + 1) & 1);   // overlaps compute below

        #pragma unroll
        for (int s = 0; s < 2; s++) {
            uint32_t sA = sb + (kt & 1) * STAGE_BYTES + s * SUB_BYTES;
            uint32_t sB = sA + 16384;

            #pragma unroll
            for (int ks = 0; ks < 4; ks++) {        // 4 x k16 per 64-wide sub-tile
                uint32_t af[2][4], bf[4][4];
                #pragma unroll
                for (int i = 0; i < 2; i++) {
                    int row = wm * 32 + i * 16 + (lid & 15);
                    int kb  = ks * 32 + ((lid >> 4) << 4);
                    ldmatrix_x4(af[i], sA + (uint32_t)(row * 128 + (kb ^ ((row & 7) << 4))));
                }
                #pragma unroll
                for (int p = 0; p < 4; p++) {       // frag pair (2p, 2p+1)
                    int n  = wn * 64 + p * 16 + (lid & 7) + (((lid >> 4) & 1) << 3);
                    int kb = ks * 32 + (((lid >> 3) & 1) << 4);
                    ldmatrix_x4(bf[p], sB + (uint32_t)(n * 128 + (kb ^ ((n & 7) << 4))));
                }
                #pragma unroll
                for (int i = 0; i < 2; i++)
                    #pragma unroll
                    for (int p = 0; p < 4; p++) {
                        mma16816(acc[i][2 * p],     af[i], &bf[p][0]);
                        mma16816(acc[i][2 * p + 1], af[i], &bf[p][2]);
                    }
            }
        }
    }

    // ---- epilogue: per-row sum / sumexp ----
    float* redS = (float*)(smc + SM_RED);            // [4][128]
    float* redE = redS + 4 * 128;                    // [4][128]
    __syncthreads();                                 // done with stage buffers
    for (int i = tid; i < 4 * 128; i += NTHREADS) { redS[i] = 0.f; redE[i] = 0.f; }
    __syncthreads();

    const int g = lid >> 2, q = lid & 3;
    #pragma unroll
    for (int i = 0; i < 2; i++) {
        #pragma unroll
        for (int half = 0; half < 2; half++) {
            int r = wm * 32 + i * 16 + g + half * 8;      // local row in [0,128)
            float s = 0.f, se = 0.f;
            #pragma unroll
            for (int j = 0; j < 8; j++) {
                float v0 = acc[i][j][half * 2 + 0];
                float v1 = acc[i][j][half * 2 + 1];
                s  += v0 + v1;
                se += __expf(v0) + __expf(v1);
            }
            s  += __shfl_xor_sync(0xFFFFFFFFu, s, 1);
            s  += __shfl_xor_sync(0xFFFFFFFFu, s, 2);
            se += __shfl_xor_sync(0xFFFFFFFFu, se, 1);
            se += __shfl_xor_sync(0xFFFFFFFFu, se, 2);
            if (q == 0) {
                redS[wn * 128 + r] = s;      // unique writer per slot
                redE[wn * 128 + r] = se;
            }
        }
    }
    __syncthreads();

    if (tid < 128) {
        int r = tid;
        float s  = redS[r] + redS[128 + r] + redS[256 + r] + redS[384 + r];
        float se = redE[r] + redE[128 + r] + redE[256 + r] + redE[384 + r];
        g_psum [(size_t)v * BB + m * BM + r] = s;
        g_psexp[(size_t)v * BB + m * BM + r] = se;
    }
}

// ===================== reductions =====================
__global__ void reduce_rows_kernel(const long long* __restrict__ y) {
    int row = blockIdx.x * blockDim.x + threadIdx.x;
    if (row >= BB) return;
    float se = 0.f, s = 0.f;
    for (int c = 0; c < NVCH; c++) {
        se += g_psexp[(size_t)c * BB + row];
        s  += g_psum [(size_t)c * BB + row];
    }
    float lse = logf(se);
    g_allp[row] = s * (1.0f / (float)VV) - lse;
    if (row < HALF) {
        bool valid = (y[row] != -100);
        g_nll[row] = valid ? (lse - g_t[row]) : 0.0f;
        g_vld[row] = valid ? 1.0f : 0.0f;
    }
}

__global__ void finalize_kernel(float* out) {
    __shared__ float sh1[256], sh2[256], sh3[256];
    int tid = threadIdx.x;
    float ce = 0.f, orx = 0.f, vc = 0.f;
    for (int i = tid; i < HALF; i += 256) {
        ce += g_nll[i];
        vc += g_vld[i];
        float ch = g_allp[i];
        float rj = g_allp[i + HALF];
        float lo = (ch - rj) - (log1pf(-expf(ch)) - log1pf(-expf(rj)));
        float ls = fminf(lo, 0.f) - log1pf(expf(-fabsf(lo)));   // log_sigmoid
        orx += 0.1f * ls;
    }
    sh1[tid] = ce; sh2[tid] = orx; sh3[tid] = vc;
    __syncthreads();
    for (int s = 128; s > 0; s >>= 1) {
        if (tid < s) { sh1[tid] += sh1[tid+s]; sh2[tid] += sh2[tid+s]; sh3[tid] += sh3[tid+s]; }
        __syncthreads();
    }
    if (tid == 0) {
        float denom = fmaxf(sh3[0], 1.0f);
        out[0] = sh1[0] / denom - sh2[0] / (float)HALF;
    }
}

// ===================== launch =====================
extern "C" void kernel_launch(void* const* d_in, const int* in_sizes, int n_in,
                              void* d_out, int out_size) {
    const float*     x = (const float*)d_in[0];
    const float*     W = (const float*)d_in[1];
    const long long* y = (const long long*)d_in[2];
    float* out = (float*)d_out;
    (void)in_sizes; (void)n_in; (void)out_size;

    cvt_x_kernel<<<2048, 256>>>(x);               // launch 0
    cvt_w_kernel<<<8192, 256>>>(W);               // launch 1
    target_kernel<<<(HALF * 32) / 256, 256>>>(x, W, y);   // launch 2 (no GEMM dep)

    cudaFuncSetAttribute(gemm_lse_kernel,
                         cudaFuncAttributeMaxDynamicSharedMemorySize, SM_ALLOC);
    gemm_lse_kernel<<<NVCH * NMT, NTHREADS, SM_ALLOC>>>();   // launch 3 (ncu window)

    reduce_rows_kernel<<<BB / 256, 256>>>(y);     // launch 4
    finalize_kernel<<<1, 256>>>(out);             // launch 5
}